// round 11
// baseline (speedup 1.0000x reference)
#include <cuda_runtime.h>
#include <cuda_fp16.h>
#include <cstdint>
#include <math.h>

#define Bv 4
#define Lv 2048
#define Kv 32
#define CD 128
#define NCH 7           // K chunks of 64
#define NKSG 28         // total k-steps of 16 (26 real)
#define GRID3 (Bv*Lv/4) // 2048 CTAs, 4 residues (128 edges) each

// Scratch (__device__ globals; no allocation allowed)
__device__ float g_atoms[Bv*Lv*5*3];
__device__ float g_ca[Bv*Lv*3];
__device__ int   g_eidx[Bv*Lv*Kv];
__device__ float g_dn[Bv*Lv*Kv];
// W in mma b-fragment layout: [ksg(28)][nt(16)][lane(32)] -> uint2 {b0,b1}, single fp16
__device__ uint2 g_Wf[NKSG*16*32];

__constant__ int c_PA[24] = {0,2,3,4,1,1,1,1,0,0,0,4,4,3,0,2,3,4,2,3,4,2,3,2};
__constant__ int c_PB[24] = {0,2,3,4,0,2,3,4,2,3,4,2,3,2,1,1,1,1,0,0,0,4,4,3};

__device__ __forceinline__ unsigned smem_u32(const void* p) {
    unsigned a;
    asm("{ .reg .u64 t; cvta.to.shared.u64 t, %1; cvt.u32.u64 %0, t; }" : "=r"(a) : "l"(p));
    return a;
}
__device__ __forceinline__ void ldsm4(unsigned* r, unsigned addr) {
    asm volatile("ldmatrix.sync.aligned.m8n8.x4.shared.b16 {%0,%1,%2,%3}, [%4];"
        : "=r"(r[0]), "=r"(r[1]), "=r"(r[2]), "=r"(r[3]) : "r"(addr));
}
__device__ __forceinline__ void mma16816(float* c, const unsigned* a, unsigned b0, unsigned b1) {
    asm volatile("mma.sync.aligned.m16n8k16.row.col.f32.f16.f16.f32 "
        "{%0,%1,%2,%3},{%4,%5,%6,%7},{%8,%9},{%0,%1,%2,%3};"
        : "+f"(c[0]), "+f"(c[1]), "+f"(c[2]), "+f"(c[3])
        : "r"(a[0]), "r"(a[1]), "r"(a[2]), "r"(a[3]), "r"(b0), "r"(b1));
}
__device__ __forceinline__ unsigned long long umin64(unsigned long long a, unsigned long long b) {
    return a < b ? a : b;
}

// ---------------------------------------------------------------------------
// k0: W_edge (416x128 f32) -> single fp16 fragments in mma b-frag layout.
// ---------------------------------------------------------------------------
__global__ void k0_prepW(const float* __restrict__ W) {
    int idx = blockIdx.x * 256 + threadIdx.x;     // NKSG*16*32 = 14336
    if (idx >= NKSG*16*32) return;
    int lane = idx & 31;
    int nt   = (idx >> 5) & 15;
    int ksg  = idx >> 9;
    int n  = nt*8 + (lane >> 2);
    int k0 = ksg*16 + (lane & 3)*2;
    unsigned r[2];
    #pragma unroll
    for (int h = 0; h < 2; h++) {
        int f0 = k0 + h*8;
        float v0 = (f0   < 416) ? W[f0 * CD + n]     : 0.0f;
        float v1 = (f0+1 < 416) ? W[(f0+1) * CD + n] : 0.0f;
        __half2 p = __floats2half2_rn(v0, v1);
        r[h] = *(unsigned*)&p;
    }
    g_Wf[idx] = make_uint2(r[0], r[1]);
}

// ---------------------------------------------------------------------------
// k1: atom table (N, Ca, C, O, Cb)
// ---------------------------------------------------------------------------
__global__ void k1_atoms(const float* __restrict__ X) {
    int i = blockIdx.x * blockDim.x + threadIdx.x;
    if (i >= Bv*Lv) return;
    const float* x = X + (size_t)i * 12;
    float Nx=x[0],Ny=x[1],Nz=x[2];
    float Ax=x[3],Ay=x[4],Az=x[5];
    float Cx=x[6],Cy=x[7],Cz=x[8];
    float Ox=x[9],Oy=x[10],Oz=x[11];
    float bx=Ax-Nx, by=Ay-Ny, bz=Az-Nz;
    float cx=Cx-Ax, cy=Cy-Ay, cz=Cz-Az;
    float ax=by*cz-bz*cy, ay=bz*cx-bx*cz, az=bx*cy-by*cx;
    float Cbx = -0.58273431f*ax + 0.56802827f*bx - 0.54067466f*cx + Ax;
    float Cby = -0.58273431f*ay + 0.56802827f*by - 0.54067466f*cy + Ay;
    float Cbz = -0.58273431f*az + 0.56802827f*bz - 0.54067466f*cz + Az;
    float* p = g_atoms + (size_t)i * 15;
    p[0]=Nx; p[1]=Ny; p[2]=Nz;
    p[3]=Ax; p[4]=Ay; p[5]=Az;
    p[6]=Cx; p[7]=Cy; p[8]=Cz;
    p[9]=Ox; p[10]=Oy; p[11]=Oz;
    p[12]=Cbx; p[13]=Cby; p[14]=Cbz;
    g_ca[i*3+0]=Ax; g_ca[i*3+1]=Ay; g_ca[i*3+2]=Az;
}

// ---------------------------------------------------------------------------
// k2: top-K, 8 rows per 256-thread CTA. Phase A: distances for 8 rows written
// straight to smem; per-row Dmax via warp reduce + smem atomicMax; per-thread
// min-key staged to smem. Phase B: 8 warps, one row each, shfl-only rounds.
// ---------------------------------------------------------------------------
__global__ void __launch_bounds__(256)
k2_topk(const float* __restrict__ mask) {
    extern __shared__ char smem_raw[];
    float* ca_s = (float*)smem_raw;                                   // 2048*3 f32 (24KB)
    float* d_s  = ca_s + Lv*3;                                        // 8*2048 f32 (64KB)
    unsigned long long* tmin = (unsigned long long*)(d_s + 8*Lv);     // 8*256 u64 (16KB)
    __shared__ int s_maxi[8];

    int tid  = threadIdx.x;
    int wid  = tid >> 5, lane = tid & 31;
    int row0 = blockIdx.x * 8;
    int b    = row0 >> 11;

    if (tid < 8) s_maxi[tid] = 0;
    const float* cab = g_ca + (size_t)b * Lv * 3;
    for (int i = tid; i < Lv*3; i += 256) ca_s[i] = cab[i];
    __syncthreads();

    float cx[8], cy[8], cz[8], mi[8];
    #pragma unroll
    for (int r = 0; r < 8; r++) {
        int li = (row0 + r) & (Lv-1);
        cx[r] = ca_s[li*3+0]; cy[r] = ca_s[li*3+1]; cz[r] = ca_s[li*3+2];
        mi[r] = mask[(size_t)row0 + r];
    }
    const float* mb = mask + (size_t)b * Lv;

    int j0 = tid * 8;
    float mbj[8];
    float lmax[8] = {0.f,0.f,0.f,0.f,0.f,0.f,0.f,0.f};
    #pragma unroll
    for (int s = 0; s < 8; s++) {
        int j = j0 + s;
        float px = ca_s[j*3+0], py = ca_s[j*3+1], pz = ca_s[j*3+2];
        mbj[s] = mb[j];
        #pragma unroll
        for (int r = 0; r < 8; r++) {
            float dx = cx[r]-px, dy = cy[r]-py, dz = cz[r]-pz;
            float d  = sqrtf(dx*dx + dy*dy + dz*dz + 1e-6f);
            float D  = mi[r] * mbj[s] * d;
            d_s[r*Lv + j] = D;
            lmax[r] = fmaxf(lmax[r], D);
        }
    }
    #pragma unroll
    for (int r = 0; r < 8; r++) {
        float v = lmax[r];
        #pragma unroll
        for (int o = 16; o; o >>= 1) v = fmaxf(v, __shfl_xor_sync(0xffffffffu, v, o));
        if (lane == 0) atomicMax(&s_maxi[r], __float_as_int(v));
    }
    __syncthreads();

    #pragma unroll
    for (int r = 0; r < 8; r++) {
        float Dmax = __int_as_float(s_maxi[r]);
        unsigned long long mn = ~0ULL;
        #pragma unroll
        for (int s = 0; s < 8; s++) {
            int j = j0 + s;
            float m2 = mi[r] * mbj[s];
            float Dadj = d_s[r*Lv + j] + (1.0f - m2) * Dmax;
            d_s[r*Lv + j] = Dadj;
            unsigned long long k = (((unsigned long long)__float_as_uint(Dadj)) << 32) | (unsigned)j;
            mn = umin64(mn, k);
        }
        tmin[r*256 + tid] = mn;
    }
    __syncthreads();

    // selection: warp r handles row r (no barriers)
    {
        int r = wid;
        int row = row0 + r;
        float* dr = d_s + r*Lv;
        unsigned long long m[8];
        #pragma unroll
        for (int s = 0; s < 8; s++) m[s] = tmin[r*256 + lane*8 + s];

        for (int rnd = 0; rnd < Kv; rnd++) {
            unsigned long long w = m[0];
            #pragma unroll
            for (int s = 1; s < 8; s++) w = umin64(w, m[s]);
            #pragma unroll
            for (int o = 16; o; o >>= 1) {
                unsigned long long v = __shfl_xor_sync(0xffffffffu, w, o);
                w = umin64(w, v);
            }
            int j = (int)(unsigned)(w & 0xffffffffu);
            if (lane == 0) {
                g_eidx[(size_t)row*Kv + rnd] = j;
                g_dn[(size_t)row*Kv + rnd]   = __uint_as_float((unsigned)(w >> 32));
            }
            int t = j >> 3;
            if ((t >> 3) == lane) {
                dr[j] = __int_as_float(0x7f800000);
                unsigned long long nm = ~0ULL;
                #pragma unroll
                for (int s = 0; s < 8; s++) {
                    int jj = t*8 + s;
                    float Dv = dr[jj];
                    unsigned long long k = (((unsigned long long)__float_as_uint(Dv)) << 32) | (unsigned)jj;
                    nm = umin64(nm, k);
                }
                m[t & 7] = nm;
            }
        }
    }
}

// ---------------------------------------------------------------------------
// k3: fused feature-build + single-pass fp16 mma GEMM + LayerNorm.
// CTA = 128 edges. Warp w owns n-cols [16w,16w+16) for all 128 rows;
// B fragments prefetched into registers at chunk start (latency hidden by
// the A-build phase), A via ldmatrix from smem.
// ---------------------------------------------------------------------------
#define S_A   0                           // 128*144 = 18432
#define S_NBA 18432                       // 128*15 f32 = 7680
#define S_QA  (S_NBA + 7680)              // 60 f32 -> 240
#define S_JV  (S_QA + 240)                // 128 int
#define S_DN  (S_JV + 512)                // 128 f32
#define S_DP  (S_DN + 512)                // 128 int
#define S_S1  (S_DP + 512)                // 128 f32 LN sum
#define S_S2  (S_S1 + 512)                // 128 f32 LN sumsq
#define S_TOT (S_S2 + 512)                // 28912 B

__global__ void __launch_bounds__(256)
k3_mma(const int* __restrict__ ridx, const int* __restrict__ chl,
       const float* __restrict__ Wpos, const float* __restrict__ bpos,
       const float* __restrict__ gamma, const float* __restrict__ beta,
       float* __restrict__ out, int write_idx) {
    extern __shared__ unsigned char sm[];
    unsigned sb = smem_u32(sm);
    int tid  = threadIdx.x;
    int wid  = tid >> 5, lane = tid & 31;
    int row0 = blockIdx.x * 4;
    int b    = row0 >> 11;

    float* nbA  = (float*)(sm + S_NBA);
    float* qa   = (float*)(sm + S_QA);
    int*   jv   = (int*)  (sm + S_JV);
    float* Dn   = (float*)(sm + S_DN);
    int*   dpos = (int*)  (sm + S_DP);
    float* s_s1 = (float*)(sm + S_S1);
    float* s_s2 = (float*)(sm + S_S2);

    if (tid < 128) {
        int r = tid >> 5;
        int brow = row0 + r;
        int j = g_eidx[(size_t)row0*Kv + tid];
        jv[tid] = j;
        Dn[tid] = g_dn[(size_t)row0*Kv + tid];
        int off = ridx[brow] - ridx[(size_t)b*Lv + j];
        int ech = (chl[brow] == chl[(size_t)b*Lv + j]) ? 1 : 0;
        int d = off + 32;
        d = d < 0 ? 0 : (d > 64 ? 64 : d);
        dpos[tid] = ech ? d : 65;
        s_s1[tid] = 0.0f;
        s_s2[tid] = 0.0f;
    }
    if (tid >= 160 && tid < 220) {
        int t = tid - 160;
        qa[t] = g_atoms[(size_t)(row0 + t/15)*15 + (t%15)];
    }
    __syncthreads();

    for (int t = tid; t < 128*15; t += 256) {
        nbA[t] = g_atoms[((size_t)b*Lv + jv[t/15])*15 + (t%15)];
    }
    __syncthreads();

    int e  = tid & 127;
    int s0 = tid >> 7;
    int r  = e >> 5;

    float acc[8][2][4];
    #pragma unroll
    for (int mt = 0; mt < 8; mt++)
        #pragma unroll
        for (int n2 = 0; n2 < 2; n2++) {
            acc[mt][n2][0]=0.f; acc[mt][n2][1]=0.f; acc[mt][n2][2]=0.f; acc[mt][n2][3]=0.f;
        }

    int arow  = lane & 15;
    int acol8 = (lane >> 4) * 8;
    const uint2* __restrict__ Wf = g_Wf;

    for (int kc = 0; kc < NCH; kc++) {
        // prefetch this chunk's B fragments (latency hidden by A build below)
        uint2 bfc[4][2];
        #pragma unroll
        for (int ks = 0; ks < 4; ks++) {
            int ksg = kc*4 + ks;
            #pragma unroll
            for (int n2 = 0; n2 < 2; n2++)
                bfc[ks][n2] = Wf[((ksg*16) + (wid*2 + n2))*32 + lane];
        }

        // A chunk build
        #pragma unroll
        for (int pp = 0; pp < 2; pp++) {
            int ss = s0 + pp*2;
            int S  = kc*4 + ss;
            if (S < 26) {
                float vals[16];
                if (S == 0) {
                    const float4* wp = (const float4*)(Wpos + dpos[e]*16);
                    const float4* bb = (const float4*)bpos;
                    #pragma unroll
                    for (int q = 0; q < 4; q++) {
                        float4 a = wp[q], c = bb[q];
                        vals[q*4+0]=a.x+c.x; vals[q*4+1]=a.y+c.y; vals[q*4+2]=a.z+c.z; vals[q*4+3]=a.w+c.w;
                    }
                } else {
                    float D;
                    if (S == 1) D = Dn[e];
                    else {
                        int p = S - 2;
                        const float* A  = qa  + r*15 + c_PA[p]*3;
                        const float* Bp = nbA + e*15 + c_PB[p]*3;
                        float dx=A[0]-Bp[0], dy=A[1]-Bp[1], dz=A[2]-Bp[2];
                        D = sqrtf(dx*dx + dy*dy + dz*dz + 1e-6f);
                    }
                    #pragma unroll
                    for (int m = 0; m < 16; m++) {
                        float mu = 2.0f + (float)m * (4.0f/3.0f);
                        float z = (D - mu) * 0.8f;
                        vals[m] = __expf(-(z*z));
                    }
                }
                unsigned byteoff = (unsigned)e*144 + (unsigned)ss*32;
                #pragma unroll
                for (int q = 0; q < 2; q++) {
                    unsigned hp[4];
                    #pragma unroll
                    for (int j4 = 0; j4 < 4; j4++) {
                        __half2 h2 = __floats2half2_rn(vals[q*8 + j4*2], vals[q*8 + j4*2 + 1]);
                        hp[j4] = *(unsigned*)&h2;
                    }
                    *(uint4*)(sm + S_A + byteoff + q*16) = make_uint4(hp[0],hp[1],hp[2],hp[3]);
                }
            }
        }
        __syncthreads();

        int nks = (kc == NCH-1) ? 2 : 4;
        for (int ks = 0; ks < nks; ks++) {
            int k0  = ks * 16;
            #pragma unroll
            for (int half = 0; half < 2; half++) {
                unsigned a[4][4];
                #pragma unroll
                for (int q = 0; q < 4; q++) {
                    int mt = half*4 + q;
                    ldsm4(a[q], sb + S_A + (unsigned)(mt*16 + arow)*144 + (unsigned)(k0 + acol8)*2);
                }
                #pragma unroll
                for (int q = 0; q < 4; q++) {
                    int mt = half*4 + q;
                    #pragma unroll
                    for (int n2 = 0; n2 < 2; n2++)
                        mma16816(acc[mt][n2], a[q], bfc[ks][n2].x, bfc[ks][n2].y);
                }
            }
        }
        __syncthreads();
    }

    if (write_idx && tid < 128) {
        out[(size_t)Bv*Lv*Kv*CD + (size_t)row0*Kv + tid] = (float)jv[tid];
    }

    // LayerNorm partials
    #pragma unroll
    for (int mt = 0; mt < 8; mt++) {
        float pA1 = acc[mt][0][0] + acc[mt][0][1] + acc[mt][1][0] + acc[mt][1][1];
        float pA2 = acc[mt][0][0]*acc[mt][0][0] + acc[mt][0][1]*acc[mt][0][1]
                  + acc[mt][1][0]*acc[mt][1][0] + acc[mt][1][1]*acc[mt][1][1];
        float pB1 = acc[mt][0][2] + acc[mt][0][3] + acc[mt][1][2] + acc[mt][1][3];
        float pB2 = acc[mt][0][2]*acc[mt][0][2] + acc[mt][0][3]*acc[mt][0][3]
                  + acc[mt][1][2]*acc[mt][1][2] + acc[mt][1][3]*acc[mt][1][3];
        #pragma unroll
        for (int o = 1; o <= 2; o <<= 1) {
            pA1 += __shfl_xor_sync(0xffffffffu, pA1, o);
            pA2 += __shfl_xor_sync(0xffffffffu, pA2, o);
            pB1 += __shfl_xor_sync(0xffffffffu, pB1, o);
            pB2 += __shfl_xor_sync(0xffffffffu, pB2, o);
        }
        if ((lane & 3) == 0) {
            int rA = mt*16 + (lane >> 2);
            atomicAdd(&s_s1[rA],     pA1);
            atomicAdd(&s_s2[rA],     pA2);
            atomicAdd(&s_s1[rA + 8], pB1);
            atomicAdd(&s_s2[rA + 8], pB2);
        }
    }
    __syncthreads();

    // normalize + write
    {
        int cb = wid*16 + 2*(lane & 3);
        float g0a = gamma[cb],     g1a = gamma[cb+1];
        float b0a = beta[cb],      b1a = beta[cb+1];
        float g0b = gamma[cb+8],   g1b = gamma[cb+9];
        float b0b = beta[cb+8],    b1b = beta[cb+9];
        #pragma unroll
        for (int mt = 0; mt < 8; mt++) {
            int rA = mt*16 + (lane >> 2);
            int rB = rA + 8;
            float muA = s_s1[rA] * (1.0f/128.0f);
            float vrA = s_s2[rA] * (1.0f/128.0f) - muA*muA;
            float ivA = 1.0f / sqrtf(vrA + 1e-5f);
            float muB = s_s1[rB] * (1.0f/128.0f);
            float vrB = s_s2[rB] * (1.0f/128.0f) - muB*muB;
            float ivB = 1.0f / sqrtf(vrB + 1e-5f);
            float* opA = out + ((size_t)row0*Kv + rA) * CD;
            float* opB = out + ((size_t)row0*Kv + rB) * CD;
            float2 oA0, oA1, oB0, oB1;
            oA0.x = (acc[mt][0][0] - muA)*ivA*g0a + b0a;
            oA0.y = (acc[mt][0][1] - muA)*ivA*g1a + b1a;
            oA1.x = (acc[mt][1][0] - muA)*ivA*g0b + b0b;
            oA1.y = (acc[mt][1][1] - muA)*ivA*g1b + b1b;
            oB0.x = (acc[mt][0][2] - muB)*ivB*g0a + b0a;
            oB0.y = (acc[mt][0][3] - muB)*ivB*g1a + b1a;
            oB1.x = (acc[mt][1][2] - muB)*ivB*g0b + b0b;
            oB1.y = (acc[mt][1][3] - muB)*ivB*g1b + b1b;
            *(float2*)(opA + cb)     = oA0;
            *(float2*)(opA + cb + 8) = oA1;
            *(float2*)(opB + cb)     = oB0;
            *(float2*)(opB + cb + 8) = oB1;
        }
    }
}

// ---------------------------------------------------------------------------
// Launch
// ---------------------------------------------------------------------------
extern "C" void kernel_launch(void* const* d_in, const int* in_sizes, int n_in,
                              void* d_out, int out_size) {
    const float* X     = (const float*)d_in[0];
    const float* mask  = (const float*)d_in[1];
    const int*   ridx  = (const int*)  d_in[2];
    const int*   chl   = (const int*)  d_in[3];
    const float* Wpos  = (const float*)d_in[4];
    const float* bpos  = (const float*)d_in[5];
    const float* Wedge = (const float*)d_in[6];
    const float* gamma = (const float*)d_in[7];
    const float* beta  = (const float*)d_in[8];
    float* out = (float*)d_out;

    const int k2_smem = (Lv*3 + 8*Lv)*4 + 8*256*8;   // 24576+65536+16384 = 106496 B
    cudaFuncSetAttribute(k2_topk, cudaFuncAttributeMaxDynamicSharedMemorySize, k2_smem);
    cudaFuncSetAttribute(k3_mma,  cudaFuncAttributeMaxDynamicSharedMemorySize, S_TOT);

    k0_prepW<<<(NKSG*16*32 + 255)/256, 256>>>(Wedge);
    k1_atoms<<<(Bv*Lv + 255)/256, 256>>>(X);
    k2_topk<<<Bv*Lv/8, 256, k2_smem>>>(mask);

    long long e_elems = (long long)Bv*Lv*Kv*CD;
    int write_idx = ((long long)out_size >= e_elems + (long long)Bv*Lv*Kv) ? 1 : 0;
    k3_mma<<<GRID3, 256, S_TOT>>>(ridx, chl, Wpos, bpos, gamma, beta, out, write_idx);
}

// round 12
// speedup vs baseline: 1.2732x; 1.2732x over previous
#include <cuda_runtime.h>
#include <cuda_fp16.h>
#include <cstdint>
#include <math.h>

#define Bv 4
#define Lv 2048
#define Kv 32
#define CD 128
#define NCH 7           // K chunks of 64
#define NKSG 28         // total k-steps of 16 (26 real)
#define GRID3 (Bv*Lv/4) // 2048 CTAs, 4 residues (128 edges) each

// Scratch (__device__ globals; no allocation allowed)
__device__ float g_atoms[Bv*Lv*5*3];
__device__ float g_ca[Bv*Lv*3];
__device__ int   g_eidx[Bv*Lv*Kv];
__device__ float g_dn[Bv*Lv*Kv];
// W in mma b-fragment layout: [ksg(28)][nt(16)][lane(32)] -> uint2 {b0,b1}, single fp16
__device__ uint2 g_Wf[NKSG*16*32];

__constant__ int c_PA[24] = {0,2,3,4,1,1,1,1,0,0,0,4,4,3,0,2,3,4,2,3,4,2,3,2};
__constant__ int c_PB[24] = {0,2,3,4,0,2,3,4,2,3,4,2,3,2,1,1,1,1,0,0,0,4,4,3};

__device__ __forceinline__ unsigned smem_u32(const void* p) {
    unsigned a;
    asm("{ .reg .u64 t; cvta.to.shared.u64 t, %1; cvt.u32.u64 %0, t; }" : "=r"(a) : "l"(p));
    return a;
}
__device__ __forceinline__ void ldsm4(unsigned* r, unsigned addr) {
    asm volatile("ldmatrix.sync.aligned.m8n8.x4.shared.b16 {%0,%1,%2,%3}, [%4];"
        : "=r"(r[0]), "=r"(r[1]), "=r"(r[2]), "=r"(r[3]) : "r"(addr));
}
__device__ __forceinline__ void mma16816(float* c, const unsigned* a, unsigned b0, unsigned b1) {
    asm volatile("mma.sync.aligned.m16n8k16.row.col.f32.f16.f16.f32 "
        "{%0,%1,%2,%3},{%4,%5,%6,%7},{%8,%9},{%0,%1,%2,%3};"
        : "+f"(c[0]), "+f"(c[1]), "+f"(c[2]), "+f"(c[3])
        : "r"(a[0]), "r"(a[1]), "r"(a[2]), "r"(a[3]), "r"(b0), "r"(b1));
}
__device__ __forceinline__ unsigned long long umin64(unsigned long long a, unsigned long long b) {
    return a < b ? a : b;
}

// ---------------------------------------------------------------------------
// k0: W_edge (416x128 f32) -> single fp16 fragments in mma b-frag layout.
// ---------------------------------------------------------------------------
__global__ void k0_prepW(const float* __restrict__ W) {
    int idx = blockIdx.x * 256 + threadIdx.x;     // NKSG*16*32 = 14336
    if (idx >= NKSG*16*32) return;
    int lane = idx & 31;
    int nt   = (idx >> 5) & 15;
    int ksg  = idx >> 9;
    int n  = nt*8 + (lane >> 2);
    int k0 = ksg*16 + (lane & 3)*2;
    unsigned r[2];
    #pragma unroll
    for (int h = 0; h < 2; h++) {
        int f0 = k0 + h*8;
        float v0 = (f0   < 416) ? W[f0 * CD + n]     : 0.0f;
        float v1 = (f0+1 < 416) ? W[(f0+1) * CD + n] : 0.0f;
        __half2 p = __floats2half2_rn(v0, v1);
        r[h] = *(unsigned*)&p;
    }
    g_Wf[idx] = make_uint2(r[0], r[1]);
}

// ---------------------------------------------------------------------------
// k1: atom table (N, Ca, C, O, Cb)
// ---------------------------------------------------------------------------
__global__ void k1_atoms(const float* __restrict__ X) {
    int i = blockIdx.x * blockDim.x + threadIdx.x;
    if (i >= Bv*Lv) return;
    const float* x = X + (size_t)i * 12;
    float Nx=x[0],Ny=x[1],Nz=x[2];
    float Ax=x[3],Ay=x[4],Az=x[5];
    float Cx=x[6],Cy=x[7],Cz=x[8];
    float Ox=x[9],Oy=x[10],Oz=x[11];
    float bx=Ax-Nx, by=Ay-Ny, bz=Az-Nz;
    float cx=Cx-Ax, cy=Cy-Ay, cz=Cz-Az;
    float ax=by*cz-bz*cy, ay=bz*cx-bx*cz, az=bx*cy-by*cx;
    float Cbx = -0.58273431f*ax + 0.56802827f*bx - 0.54067466f*cx + Ax;
    float Cby = -0.58273431f*ay + 0.56802827f*by - 0.54067466f*cy + Ay;
    float Cbz = -0.58273431f*az + 0.56802827f*bz - 0.54067466f*cz + Az;
    float* p = g_atoms + (size_t)i * 15;
    p[0]=Nx; p[1]=Ny; p[2]=Nz;
    p[3]=Ax; p[4]=Ay; p[5]=Az;
    p[6]=Cx; p[7]=Cy; p[8]=Cz;
    p[9]=Ox; p[10]=Oy; p[11]=Oz;
    p[12]=Cbx; p[13]=Cby; p[14]=Cbz;
    g_ca[i*3+0]=Ax; g_ca[i*3+1]=Ay; g_ca[i*3+2]=Az;
}

// ---------------------------------------------------------------------------
// k2: top-K, 4 rows per 256-thread CTA (proven R10 version).
// ---------------------------------------------------------------------------
__global__ void __launch_bounds__(256)
k2_topk(const float* __restrict__ mask) {
    extern __shared__ char smem_raw[];
    float* ca_s = (float*)smem_raw;
    float* d_s  = ca_s + Lv*3;
    unsigned long long* tmin = (unsigned long long*)(d_s + 4*Lv);
    __shared__ int s_maxi[4];

    int tid  = threadIdx.x;
    int wid  = tid >> 5, lane = tid & 31;
    int row0 = blockIdx.x * 4;
    int b    = row0 >> 11;

    if (tid < 4) s_maxi[tid] = 0;
    const float* cab = g_ca + (size_t)b * Lv * 3;
    for (int i = tid; i < Lv*3; i += 256) ca_s[i] = cab[i];
    __syncthreads();

    float cx[4], cy[4], cz[4], mi[4];
    #pragma unroll
    for (int r = 0; r < 4; r++) {
        int li = (row0 + r) & (Lv-1);
        cx[r] = ca_s[li*3+0]; cy[r] = ca_s[li*3+1]; cz[r] = ca_s[li*3+2];
        mi[r] = mask[(size_t)row0 + r];
    }
    const float* mb = mask + (size_t)b * Lv;

    int j0 = tid * 8;
    float Dreg[4][8], mbj[8];
    float lmax[4] = {0.f, 0.f, 0.f, 0.f};
    #pragma unroll
    for (int s = 0; s < 8; s++) {
        int j = j0 + s;
        float px = ca_s[j*3+0], py = ca_s[j*3+1], pz = ca_s[j*3+2];
        mbj[s] = mb[j];
        #pragma unroll
        for (int r = 0; r < 4; r++) {
            float dx = cx[r]-px, dy = cy[r]-py, dz = cz[r]-pz;
            float d  = sqrtf(dx*dx + dy*dy + dz*dz + 1e-6f);
            float D  = mi[r] * mbj[s] * d;
            Dreg[r][s] = D;
            lmax[r] = fmaxf(lmax[r], D);
        }
    }
    #pragma unroll
    for (int r = 0; r < 4; r++) {
        float v = lmax[r];
        #pragma unroll
        for (int o = 16; o; o >>= 1) v = fmaxf(v, __shfl_xor_sync(0xffffffffu, v, o));
        if (lane == 0) atomicMax(&s_maxi[r], __float_as_int(v));
    }
    __syncthreads();

    #pragma unroll
    for (int r = 0; r < 4; r++) {
        float Dmax = __int_as_float(s_maxi[r]);
        unsigned long long mn = ~0ULL;
        #pragma unroll
        for (int s = 0; s < 8; s++) {
            int j = j0 + s;
            float m2 = mi[r] * mbj[s];
            float Dadj = Dreg[r][s] + (1.0f - m2) * Dmax;
            d_s[r*Lv + j] = Dadj;
            unsigned long long k = (((unsigned long long)__float_as_uint(Dadj)) << 32) | (unsigned)j;
            mn = umin64(mn, k);
        }
        tmin[r*256 + tid] = mn;
    }
    __syncthreads();

    if (wid < 4) {
        int r = wid;
        int row = row0 + r;
        float* dr = d_s + r*Lv;
        unsigned long long m[8];
        #pragma unroll
        for (int s = 0; s < 8; s++) m[s] = tmin[r*256 + lane*8 + s];

        for (int rnd = 0; rnd < Kv; rnd++) {
            unsigned long long w = m[0];
            #pragma unroll
            for (int s = 1; s < 8; s++) w = umin64(w, m[s]);
            #pragma unroll
            for (int o = 16; o; o >>= 1) {
                unsigned long long v = __shfl_xor_sync(0xffffffffu, w, o);
                w = umin64(w, v);
            }
            int j = (int)(unsigned)(w & 0xffffffffu);
            if (lane == 0) {
                g_eidx[(size_t)row*Kv + rnd] = j;
                g_dn[(size_t)row*Kv + rnd]   = __uint_as_float((unsigned)(w >> 32));
            }
            int t = j >> 3;
            if ((t >> 3) == lane) {
                dr[j] = __int_as_float(0x7f800000);
                unsigned long long nm = ~0ULL;
                #pragma unroll
                for (int s = 0; s < 8; s++) {
                    int jj = t*8 + s;
                    float Dv = dr[jj];
                    unsigned long long k = (((unsigned long long)__float_as_uint(Dv)) << 32) | (unsigned)jj;
                    nm = umin64(nm, k);
                }
                m[t & 7] = nm;
            }
        }
    }
}

// ---------------------------------------------------------------------------
// k3: fused feature-build + single-pass fp16 mma GEMM + LayerNorm.
// CTA = 128 edges. Warp grid 2(M) x 4(N): warp (wr,wc) owns rows
// [wr*64, wr*64+64) x cols [wc*32, wc*32+32). A LDSM replication is 4x
// (was 8x); B fragments from g_Wf per k-step (R10-proven placement).
// ---------------------------------------------------------------------------
#define S_A   0                           // 128*144 = 18432
#define S_NBA 18432                       // 128*15 f32 = 7680
#define S_QA  (S_NBA + 7680)              // 60 f32 -> 240
#define S_JV  (S_QA + 240)                // 128 int
#define S_DN  (S_JV + 512)                // 128 f32
#define S_DP  (S_DN + 512)                // 128 int
#define S_S1  (S_DP + 512)                // 128 f32 LN sum
#define S_S2  (S_S1 + 512)                // 128 f32 LN sumsq
#define S_TOT (S_S2 + 512)                // 28912 B

__global__ void __launch_bounds__(256)
k3_mma(const int* __restrict__ ridx, const int* __restrict__ chl,
       const float* __restrict__ Wpos, const float* __restrict__ bpos,
       const float* __restrict__ gamma, const float* __restrict__ beta,
       float* __restrict__ out, int write_idx) {
    extern __shared__ unsigned char sm[];
    unsigned sb = smem_u32(sm);
    int tid  = threadIdx.x;
    int wid  = tid >> 5, lane = tid & 31;
    int wr   = wid >> 2;                 // M group: rows wr*64..wr*64+63
    int wc   = wid & 3;                  // N group: cols wc*32..wc*32+31
    int row0 = blockIdx.x * 4;
    int b    = row0 >> 11;

    float* nbA  = (float*)(sm + S_NBA);
    float* qa   = (float*)(sm + S_QA);
    int*   jv   = (int*)  (sm + S_JV);
    float* Dn   = (float*)(sm + S_DN);
    int*   dpos = (int*)  (sm + S_DP);
    float* s_s1 = (float*)(sm + S_S1);
    float* s_s2 = (float*)(sm + S_S2);

    if (tid < 128) {
        int r = tid >> 5;
        int brow = row0 + r;
        int j = g_eidx[(size_t)row0*Kv + tid];
        jv[tid] = j;
        Dn[tid] = g_dn[(size_t)row0*Kv + tid];
        int off = ridx[brow] - ridx[(size_t)b*Lv + j];
        int ech = (chl[brow] == chl[(size_t)b*Lv + j]) ? 1 : 0;
        int d = off + 32;
        d = d < 0 ? 0 : (d > 64 ? 64 : d);
        dpos[tid] = ech ? d : 65;
        s_s1[tid] = 0.0f;
        s_s2[tid] = 0.0f;
    }
    if (tid >= 160 && tid < 220) {
        int t = tid - 160;
        qa[t] = g_atoms[(size_t)(row0 + t/15)*15 + (t%15)];
    }
    __syncthreads();

    for (int t = tid; t < 128*15; t += 256) {
        nbA[t] = g_atoms[((size_t)b*Lv + jv[t/15])*15 + (t%15)];
    }
    __syncthreads();

    int e  = tid & 127;
    int s0 = tid >> 7;
    int r  = e >> 5;

    // acc[mt][nt][4]: rows wr*64 + mt*16, cols wc*32 + nt*8
    float acc[4][4][4];
    #pragma unroll
    for (int mt = 0; mt < 4; mt++)
        #pragma unroll
        for (int nt = 0; nt < 4; nt++) {
            acc[mt][nt][0]=0.f; acc[mt][nt][1]=0.f; acc[mt][nt][2]=0.f; acc[mt][nt][3]=0.f;
        }

    int arow  = lane & 15;
    int acol8 = (lane >> 4) * 8;
    unsigned aBase = sb + S_A + (unsigned)(wr*64)*144;
    const uint2* __restrict__ Wf = g_Wf;

    for (int kc = 0; kc < NCH; kc++) {
        // A chunk build
        #pragma unroll
        for (int pp = 0; pp < 2; pp++) {
            int ss = s0 + pp*2;
            int S  = kc*4 + ss;
            if (S < 26) {
                float vals[16];
                if (S == 0) {
                    const float4* wp = (const float4*)(Wpos + dpos[e]*16);
                    const float4* bb = (const float4*)bpos;
                    #pragma unroll
                    for (int q = 0; q < 4; q++) {
                        float4 a = wp[q], c = bb[q];
                        vals[q*4+0]=a.x+c.x; vals[q*4+1]=a.y+c.y; vals[q*4+2]=a.z+c.z; vals[q*4+3]=a.w+c.w;
                    }
                } else {
                    float D;
                    if (S == 1) D = Dn[e];
                    else {
                        int p = S - 2;
                        const float* A  = qa  + r*15 + c_PA[p]*3;
                        const float* Bp = nbA + e*15 + c_PB[p]*3;
                        float dx=A[0]-Bp[0], dy=A[1]-Bp[1], dz=A[2]-Bp[2];
                        D = sqrtf(dx*dx + dy*dy + dz*dz + 1e-6f);
                    }
                    #pragma unroll
                    for (int m = 0; m < 16; m++) {
                        float mu = 2.0f + (float)m * (4.0f/3.0f);
                        float z = (D - mu) * 0.8f;
                        vals[m] = __expf(-(z*z));
                    }
                }
                unsigned byteoff = (unsigned)e*144 + (unsigned)ss*32;
                #pragma unroll
                for (int q = 0; q < 2; q++) {
                    unsigned hp[4];
                    #pragma unroll
                    for (int j4 = 0; j4 < 4; j4++) {
                        __half2 h2 = __floats2half2_rn(vals[q*8 + j4*2], vals[q*8 + j4*2 + 1]);
                        hp[j4] = *(unsigned*)&h2;
                    }
                    *(uint4*)(sm + S_A + byteoff + q*16) = make_uint4(hp[0],hp[1],hp[2],hp[3]);
                }
            }
        }
        __syncthreads();

        int nks = (kc == NCH-1) ? 2 : 4;
        for (int ks = 0; ks < nks; ks++) {
            int ksg = kc*4 + ks;
            int k0  = ks * 16;
            // this warp's 4 B n-tiles for this k-step (L2-hot)
            uint2 bf[4];
            #pragma unroll
            for (int nt = 0; nt < 4; nt++)
                bf[nt] = Wf[((ksg*16) + (wc*4 + nt))*32 + lane];
            // A fragments: 4 m-tiles in this warp's 64-row band
            unsigned a[4][4];
            #pragma unroll
            for (int mt = 0; mt < 4; mt++)
                ldsm4(a[mt], aBase + (unsigned)(mt*16 + arow)*144 + (unsigned)(k0 + acol8)*2);
            #pragma unroll
            for (int mt = 0; mt < 4; mt++)
                #pragma unroll
                for (int nt = 0; nt < 4; nt++)
                    mma16816(acc[mt][nt], a[mt], bf[nt].x, bf[nt].y);
        }
        __syncthreads();
    }

    if (write_idx && tid < 128) {
        out[(size_t)Bv*Lv*Kv*CD + (size_t)row0*Kv + tid] = (float)jv[tid];
    }

    // LayerNorm partials: warp covers 32 cols for rows in its 64-row band
    #pragma unroll
    for (int mt = 0; mt < 4; mt++) {
        float pA1=0.f, pA2=0.f, pB1=0.f, pB2=0.f;
        #pragma unroll
        for (int nt = 0; nt < 4; nt++) {
            float v0 = acc[mt][nt][0], v1 = acc[mt][nt][1];
            float v2 = acc[mt][nt][2], v3 = acc[mt][nt][3];
            pA1 += v0 + v1;  pA2 += v0*v0 + v1*v1;
            pB1 += v2 + v3;  pB2 += v2*v2 + v3*v3;
        }
        #pragma unroll
        for (int o = 1; o <= 2; o <<= 1) {
            pA1 += __shfl_xor_sync(0xffffffffu, pA1, o);
            pA2 += __shfl_xor_sync(0xffffffffu, pA2, o);
            pB1 += __shfl_xor_sync(0xffffffffu, pB1, o);
            pB2 += __shfl_xor_sync(0xffffffffu, pB2, o);
        }
        if ((lane & 3) == 0) {
            int rA = wr*64 + mt*16 + (lane >> 2);
            atomicAdd(&s_s1[rA],     pA1);
            atomicAdd(&s_s2[rA],     pA2);
            atomicAdd(&s_s1[rA + 8], pB1);
            atomicAdd(&s_s2[rA + 8], pB2);
        }
    }
    __syncthreads();

    // normalize + write: warp writes its 32-col slice for its 64-row band
    {
        int cb = wc*32 + 2*(lane & 3);
        float gv[4][2], bv[4][2];
        #pragma unroll
        for (int nt = 0; nt < 4; nt++) {
            gv[nt][0] = gamma[cb + nt*8];  gv[nt][1] = gamma[cb + nt*8 + 1];
            bv[nt][0] = beta[cb + nt*8];   bv[nt][1] = beta[cb + nt*8 + 1];
        }
        #pragma unroll
        for (int mt = 0; mt < 4; mt++) {
            int rA = wr*64 + mt*16 + (lane >> 2);
            int rB = rA + 8;
            float muA = s_s1[rA] * (1.0f/128.0f);
            float vrA = s_s2[rA] * (1.0f/128.0f) - muA*muA;
            float ivA = 1.0f / sqrtf(vrA + 1e-5f);
            float muB = s_s1[rB] * (1.0f/128.0f);
            float vrB = s_s2[rB] * (1.0f/128.0f) - muB*muB;
            float ivB = 1.0f / sqrtf(vrB + 1e-5f);
            float* opA = out + ((size_t)row0*Kv + rA) * CD;
            float* opB = out + ((size_t)row0*Kv + rB) * CD;
            #pragma unroll
            for (int nt = 0; nt < 4; nt++) {
                int c = cb + nt*8;
                float2 oA, oB;
                oA.x = (acc[mt][nt][0] - muA)*ivA*gv[nt][0] + bv[nt][0];
                oA.y = (acc[mt][nt][1] - muA)*ivA*gv[nt][1] + bv[nt][1];
                oB.x = (acc[mt][nt][2] - muB)*ivB*gv[nt][0] + bv[nt][0];
                oB.y = (acc[mt][nt][3] - muB)*ivB*gv[nt][1] + bv[nt][1];
                *(float2*)(opA + c) = oA;
                *(float2*)(opB + c) = oB;
            }
        }
    }
}

// ---------------------------------------------------------------------------
// Launch
// ---------------------------------------------------------------------------
extern "C" void kernel_launch(void* const* d_in, const int* in_sizes, int n_in,
                              void* d_out, int out_size) {
    const float* X     = (const float*)d_in[0];
    const float* mask  = (const float*)d_in[1];
    const int*   ridx  = (const int*)  d_in[2];
    const int*   chl   = (const int*)  d_in[3];
    const float* Wpos  = (const float*)d_in[4];
    const float* bpos  = (const float*)d_in[5];
    const float* Wedge = (const float*)d_in[6];
    const float* gamma = (const float*)d_in[7];
    const float* beta  = (const float*)d_in[8];
    float* out = (float*)d_out;

    const int k2_smem = (Lv*3 + 4*Lv)*4 + 4*256*8;   // 65536 B
    cudaFuncSetAttribute(k2_topk, cudaFuncAttributeMaxDynamicSharedMemorySize, k2_smem);
    cudaFuncSetAttribute(k3_mma,  cudaFuncAttributeMaxDynamicSharedMemorySize, S_TOT);

    k0_prepW<<<(NKSG*16*32 + 255)/256, 256>>>(Wedge);
    k1_atoms<<<(Bv*Lv + 255)/256, 256>>>(X);
    k2_topk<<<Bv*Lv/4, 256, k2_smem>>>(mask);

    long long e_elems = (long long)Bv*Lv*Kv*CD;
    int write_idx = ((long long)out_size >= e_elems + (long long)Bv*Lv*Kv) ? 1 : 0;
    k3_mma<<<GRID3, 256, S_TOT>>>(ridx, chl, Wpos, bpos, gamma, beta, out, write_idx);
}

// round 13
// speedup vs baseline: 1.3073x; 1.0268x over previous
#include <cuda_runtime.h>
#include <cuda_fp16.h>
#include <cstdint>
#include <math.h>

#define Bv 4
#define Lv 2048
#define Kv 32
#define CD 128
#define NCH 7           // K chunks of 64
#define NKSG 28         // total k-steps of 16 (26 real)
#define GRID3 (Bv*Lv/4) // 2048 CTAs, 4 residues (128 edges) each

// Scratch (__device__ globals; no allocation allowed)
__device__ float g_atoms[Bv*Lv*5*3];
__device__ float g_ca[Bv*Lv*3];
__device__ int   g_eidx[Bv*Lv*Kv];
__device__ float g_dn[Bv*Lv*Kv];
// W in mma b-fragment layout: [ksg(28)][nt(16)][lane(32)] -> uint2 {b0,b1}, single fp16
__device__ uint2 g_Wf[NKSG*16*32];

__constant__ int c_PA[24] = {0,2,3,4,1,1,1,1,0,0,0,4,4,3,0,2,3,4,2,3,4,2,3,2};
__constant__ int c_PB[24] = {0,2,3,4,0,2,3,4,2,3,4,2,3,2,1,1,1,1,0,0,0,4,4,3};

__device__ __forceinline__ unsigned smem_u32(const void* p) {
    unsigned a;
    asm("{ .reg .u64 t; cvta.to.shared.u64 t, %1; cvt.u32.u64 %0, t; }" : "=r"(a) : "l"(p));
    return a;
}
__device__ __forceinline__ void ldsm4(unsigned* r, unsigned addr) {
    asm volatile("ldmatrix.sync.aligned.m8n8.x4.shared.b16 {%0,%1,%2,%3}, [%4];"
        : "=r"(r[0]), "=r"(r[1]), "=r"(r[2]), "=r"(r[3]) : "r"(addr));
}
__device__ __forceinline__ void mma16816(float* c, const unsigned* a, unsigned b0, unsigned b1) {
    asm volatile("mma.sync.aligned.m16n8k16.row.col.f32.f16.f16.f32 "
        "{%0,%1,%2,%3},{%4,%5,%6,%7},{%8,%9},{%0,%1,%2,%3};"
        : "+f"(c[0]), "+f"(c[1]), "+f"(c[2]), "+f"(c[3])
        : "r"(a[0]), "r"(a[1]), "r"(a[2]), "r"(a[3]), "r"(b0), "r"(b1));
}
__device__ __forceinline__ unsigned long long umin64(unsigned long long a, unsigned long long b) {
    return a < b ? a : b;
}

// ---------------------------------------------------------------------------
// k0: W_edge (416x128 f32) -> single fp16 fragments in mma b-frag layout.
// ---------------------------------------------------------------------------
__global__ void k0_prepW(const float* __restrict__ W) {
    int idx = blockIdx.x * 256 + threadIdx.x;     // NKSG*16*32 = 14336
    if (idx >= NKSG*16*32) return;
    int lane = idx & 31;
    int nt   = (idx >> 5) & 15;
    int ksg  = idx >> 9;
    int n  = nt*8 + (lane >> 2);
    int k0 = ksg*16 + (lane & 3)*2;
    unsigned r[2];
    #pragma unroll
    for (int h = 0; h < 2; h++) {
        int f0 = k0 + h*8;
        float v0 = (f0   < 416) ? W[f0 * CD + n]     : 0.0f;
        float v1 = (f0+1 < 416) ? W[(f0+1) * CD + n] : 0.0f;
        __half2 p = __floats2half2_rn(v0, v1);
        r[h] = *(unsigned*)&p;
    }
    g_Wf[idx] = make_uint2(r[0], r[1]);
}

// ---------------------------------------------------------------------------
// k1: atom table (N, Ca, C, O, Cb)
// ---------------------------------------------------------------------------
__global__ void k1_atoms(const float* __restrict__ X) {
    int i = blockIdx.x * blockDim.x + threadIdx.x;
    if (i >= Bv*Lv) return;
    const float* x = X + (size_t)i * 12;
    float Nx=x[0],Ny=x[1],Nz=x[2];
    float Ax=x[3],Ay=x[4],Az=x[5];
    float Cx=x[6],Cy=x[7],Cz=x[8];
    float Ox=x[9],Oy=x[10],Oz=x[11];
    float bx=Ax-Nx, by=Ay-Ny, bz=Az-Nz;
    float cx=Cx-Ax, cy=Cy-Ay, cz=Cz-Az;
    float ax=by*cz-bz*cy, ay=bz*cx-bx*cz, az=bx*cy-by*cx;
    float Cbx = -0.58273431f*ax + 0.56802827f*bx - 0.54067466f*cx + Ax;
    float Cby = -0.58273431f*ay + 0.56802827f*by - 0.54067466f*cy + Ay;
    float Cbz = -0.58273431f*az + 0.56802827f*bz - 0.54067466f*cz + Az;
    float* p = g_atoms + (size_t)i * 15;
    p[0]=Nx; p[1]=Ny; p[2]=Nz;
    p[3]=Ax; p[4]=Ay; p[5]=Az;
    p[6]=Cx; p[7]=Cy; p[8]=Cz;
    p[9]=Ox; p[10]=Oy; p[11]=Oz;
    p[12]=Cbx; p[13]=Cby; p[14]=Cbz;
    g_ca[i*3+0]=Ax; g_ca[i*3+1]=Ay; g_ca[i*3+2]=Az;
}

// ---------------------------------------------------------------------------
// k2: top-K, 4 rows per 256-thread CTA (proven R10 version).
// ---------------------------------------------------------------------------
__global__ void __launch_bounds__(256)
k2_topk(const float* __restrict__ mask) {
    extern __shared__ char smem_raw[];
    float* ca_s = (float*)smem_raw;
    float* d_s  = ca_s + Lv*3;
    unsigned long long* tmin = (unsigned long long*)(d_s + 4*Lv);
    __shared__ int s_maxi[4];

    int tid  = threadIdx.x;
    int wid  = tid >> 5, lane = tid & 31;
    int row0 = blockIdx.x * 4;
    int b    = row0 >> 11;

    if (tid < 4) s_maxi[tid] = 0;
    const float* cab = g_ca + (size_t)b * Lv * 3;
    for (int i = tid; i < Lv*3; i += 256) ca_s[i] = cab[i];
    __syncthreads();

    float cx[4], cy[4], cz[4], mi[4];
    #pragma unroll
    for (int r = 0; r < 4; r++) {
        int li = (row0 + r) & (Lv-1);
        cx[r] = ca_s[li*3+0]; cy[r] = ca_s[li*3+1]; cz[r] = ca_s[li*3+2];
        mi[r] = mask[(size_t)row0 + r];
    }
    const float* mb = mask + (size_t)b * Lv;

    int j0 = tid * 8;
    float Dreg[4][8], mbj[8];
    float lmax[4] = {0.f, 0.f, 0.f, 0.f};
    #pragma unroll
    for (int s = 0; s < 8; s++) {
        int j = j0 + s;
        float px = ca_s[j*3+0], py = ca_s[j*3+1], pz = ca_s[j*3+2];
        mbj[s] = mb[j];
        #pragma unroll
        for (int r = 0; r < 4; r++) {
            float dx = cx[r]-px, dy = cy[r]-py, dz = cz[r]-pz;
            float d  = sqrtf(dx*dx + dy*dy + dz*dz + 1e-6f);
            float D  = mi[r] * mbj[s] * d;
            Dreg[r][s] = D;
            lmax[r] = fmaxf(lmax[r], D);
        }
    }
    #pragma unroll
    for (int r = 0; r < 4; r++) {
        float v = lmax[r];
        #pragma unroll
        for (int o = 16; o; o >>= 1) v = fmaxf(v, __shfl_xor_sync(0xffffffffu, v, o));
        if (lane == 0) atomicMax(&s_maxi[r], __float_as_int(v));
    }
    __syncthreads();

    #pragma unroll
    for (int r = 0; r < 4; r++) {
        float Dmax = __int_as_float(s_maxi[r]);
        unsigned long long mn = ~0ULL;
        #pragma unroll
        for (int s = 0; s < 8; s++) {
            int j = j0 + s;
            float m2 = mi[r] * mbj[s];
            float Dadj = Dreg[r][s] + (1.0f - m2) * Dmax;
            d_s[r*Lv + j] = Dadj;
            unsigned long long k = (((unsigned long long)__float_as_uint(Dadj)) << 32) | (unsigned)j;
            mn = umin64(mn, k);
        }
        tmin[r*256 + tid] = mn;
    }
    __syncthreads();

    if (wid < 4) {
        int r = wid;
        int row = row0 + r;
        float* dr = d_s + r*Lv;
        unsigned long long m[8];
        #pragma unroll
        for (int s = 0; s < 8; s++) m[s] = tmin[r*256 + lane*8 + s];

        for (int rnd = 0; rnd < Kv; rnd++) {
            unsigned long long w = m[0];
            #pragma unroll
            for (int s = 1; s < 8; s++) w = umin64(w, m[s]);
            #pragma unroll
            for (int o = 16; o; o >>= 1) {
                unsigned long long v = __shfl_xor_sync(0xffffffffu, w, o);
                w = umin64(w, v);
            }
            int j = (int)(unsigned)(w & 0xffffffffu);
            if (lane == 0) {
                g_eidx[(size_t)row*Kv + rnd] = j;
                g_dn[(size_t)row*Kv + rnd]   = __uint_as_float((unsigned)(w >> 32));
            }
            int t = j >> 3;
            if ((t >> 3) == lane) {
                dr[j] = __int_as_float(0x7f800000);
                unsigned long long nm = ~0ULL;
                #pragma unroll
                for (int s = 0; s < 8; s++) {
                    int jj = t*8 + s;
                    float Dv = dr[jj];
                    unsigned long long k = (((unsigned long long)__float_as_uint(Dv)) << 32) | (unsigned)jj;
                    nm = umin64(nm, k);
                }
                m[t & 7] = nm;
            }
        }
    }
}

// ---------------------------------------------------------------------------
// k3: fused feature-build + single-pass fp16 mma GEMM + LayerNorm.
// Warp grid 2(M) x 4(N) (R12-proven). A tile DOUBLE-BUFFERED: per barrier
// region the MMA for chunk kc (buf kc&1) and the build for kc+1 (other buf)
// coexist, letting tensor and MUFU/FMA pipes overlap. 8 barriers vs 14.
// ---------------------------------------------------------------------------
#define S_A0  0                           // 128*144 = 18432
#define S_A1  18432                       // second A buffer
#define S_NBA 36864                       // 128*15 f32 = 7680
#define S_QA  (S_NBA + 7680)              // 60 f32 -> 240
#define S_JV  (S_QA + 240)                // 128 int
#define S_DN  (S_JV + 512)                // 128 f32
#define S_DP  (S_DN + 512)                // 128 int
#define S_S1  (S_DP + 512)                // 128 f32 LN sum
#define S_S2  (S_S1 + 512)                // 128 f32 LN sumsq
#define S_TOT (S_S2 + 512)                // 47344 B

__global__ void __launch_bounds__(256, 2)
k3_mma(const int* __restrict__ ridx, const int* __restrict__ chl,
       const float* __restrict__ Wpos, const float* __restrict__ bpos,
       const float* __restrict__ gamma, const float* __restrict__ beta,
       float* __restrict__ out, int write_idx) {
    extern __shared__ unsigned char sm[];
    unsigned sb = smem_u32(sm);
    int tid  = threadIdx.x;
    int wid  = tid >> 5, lane = tid & 31;
    int wr   = wid >> 2;                 // M group: rows wr*64..wr*64+63
    int wc   = wid & 3;                  // N group: cols wc*32..wc*32+31
    int row0 = blockIdx.x * 4;
    int b    = row0 >> 11;

    float* nbA  = (float*)(sm + S_NBA);
    float* qa   = (float*)(sm + S_QA);
    int*   jv   = (int*)  (sm + S_JV);
    float* Dn   = (float*)(sm + S_DN);
    int*   dpos = (int*)  (sm + S_DP);
    float* s_s1 = (float*)(sm + S_S1);
    float* s_s2 = (float*)(sm + S_S2);

    if (tid < 128) {
        int r = tid >> 5;
        int brow = row0 + r;
        int j = g_eidx[(size_t)row0*Kv + tid];
        jv[tid] = j;
        Dn[tid] = g_dn[(size_t)row0*Kv + tid];
        int off = ridx[brow] - ridx[(size_t)b*Lv + j];
        int ech = (chl[brow] == chl[(size_t)b*Lv + j]) ? 1 : 0;
        int d = off + 32;
        d = d < 0 ? 0 : (d > 64 ? 64 : d);
        dpos[tid] = ech ? d : 65;
        s_s1[tid] = 0.0f;
        s_s2[tid] = 0.0f;
    }
    if (tid >= 160 && tid < 220) {
        int t = tid - 160;
        qa[t] = g_atoms[(size_t)(row0 + t/15)*15 + (t%15)];
    }
    __syncthreads();

    for (int t = tid; t < 128*15; t += 256) {
        nbA[t] = g_atoms[((size_t)b*Lv + jv[t/15])*15 + (t%15)];
    }
    __syncthreads();

    int e  = tid & 127;
    int s0 = tid >> 7;
    int r  = e >> 5;

    // build one 64-wide A chunk (this thread's 2 sub-blocks) into buffer abuf
    auto build_chunk = [&](int kcb, unsigned abuf) {
        #pragma unroll
        for (int pp = 0; pp < 2; pp++) {
            int ss = s0 + pp*2;
            int S  = kcb*4 + ss;
            if (S < 26) {
                float vals[16];
                if (S == 0) {
                    const float4* wp = (const float4*)(Wpos + dpos[e]*16);
                    const float4* bb = (const float4*)bpos;
                    #pragma unroll
                    for (int q = 0; q < 4; q++) {
                        float4 a = wp[q], c = bb[q];
                        vals[q*4+0]=a.x+c.x; vals[q*4+1]=a.y+c.y; vals[q*4+2]=a.z+c.z; vals[q*4+3]=a.w+c.w;
                    }
                } else {
                    float D;
                    if (S == 1) D = Dn[e];
                    else {
                        int p = S - 2;
                        const float* A  = qa  + r*15 + c_PA[p]*3;
                        const float* Bp = nbA + e*15 + c_PB[p]*3;
                        float dx=A[0]-Bp[0], dy=A[1]-Bp[1], dz=A[2]-Bp[2];
                        D = sqrtf(dx*dx + dy*dy + dz*dz + 1e-6f);
                    }
                    #pragma unroll
                    for (int m = 0; m < 16; m++) {
                        float mu = 2.0f + (float)m * (4.0f/3.0f);
                        float z = (D - mu) * 0.8f;
                        vals[m] = __expf(-(z*z));
                    }
                }
                unsigned byteoff = abuf + (unsigned)e*144 + (unsigned)ss*32;
                #pragma unroll
                for (int q = 0; q < 2; q++) {
                    unsigned hp[4];
                    #pragma unroll
                    for (int j4 = 0; j4 < 4; j4++) {
                        __half2 h2 = __floats2half2_rn(vals[q*8 + j4*2], vals[q*8 + j4*2 + 1]);
                        hp[j4] = *(unsigned*)&h2;
                    }
                    *(uint4*)(sm + byteoff + q*16) = make_uint4(hp[0],hp[1],hp[2],hp[3]);
                }
            }
        }
    };

    float acc[4][4][4];
    #pragma unroll
    for (int mt = 0; mt < 4; mt++)
        #pragma unroll
        for (int nt = 0; nt < 4; nt++) {
            acc[mt][nt][0]=0.f; acc[mt][nt][1]=0.f; acc[mt][nt][2]=0.f; acc[mt][nt][3]=0.f;
        }

    int arow  = lane & 15;
    int acol8 = (lane >> 4) * 8;
    const uint2* __restrict__ Wf = g_Wf;

    build_chunk(0, S_A0);
    __syncthreads();

    for (int kc = 0; kc < NCH; kc++) {
        unsigned cur = (kc & 1) ? S_A1 : S_A0;
        unsigned nxt = (kc & 1) ? S_A0 : S_A1;
        unsigned aBase = sb + cur + (unsigned)(wr*64)*144;

        // MMA chunk kc (reads cur) — interleaves with build below (writes nxt)
        int nks = (kc == NCH-1) ? 2 : 4;
        for (int ks = 0; ks < nks; ks++) {
            int ksg = kc*4 + ks;
            int k0  = ks * 16;
            uint2 bf[4];
            #pragma unroll
            for (int nt = 0; nt < 4; nt++)
                bf[nt] = Wf[((ksg*16) + (wc*4 + nt))*32 + lane];
            unsigned a[4][4];
            #pragma unroll
            for (int mt = 0; mt < 4; mt++)
                ldsm4(a[mt], aBase + (unsigned)(mt*16 + arow)*144 + (unsigned)(k0 + acol8)*2);
            #pragma unroll
            for (int mt = 0; mt < 4; mt++)
                #pragma unroll
                for (int nt = 0; nt < 4; nt++)
                    mma16816(acc[mt][nt], a[mt], bf[nt].x, bf[nt].y);
        }

        // build next chunk into the other buffer (no dependency on MMA above)
        if (kc + 1 < NCH) build_chunk(kc + 1, nxt);

        __syncthreads();
    }

    if (write_idx && tid < 128) {
        out[(size_t)Bv*Lv*Kv*CD + (size_t)row0*Kv + tid] = (float)jv[tid];
    }

    // LayerNorm partials: warp covers 32 cols for rows in its 64-row band
    #pragma unroll
    for (int mt = 0; mt < 4; mt++) {
        float pA1=0.f, pA2=0.f, pB1=0.f, pB2=0.f;
        #pragma unroll
        for (int nt = 0; nt < 4; nt++) {
            float v0 = acc[mt][nt][0], v1 = acc[mt][nt][1];
            float v2 = acc[mt][nt][2], v3 = acc[mt][nt][3];
            pA1 += v0 + v1;  pA2 += v0*v0 + v1*v1;
            pB1 += v2 + v3;  pB2 += v2*v2 + v3*v3;
        }
        #pragma unroll
        for (int o = 1; o <= 2; o <<= 1) {
            pA1 += __shfl_xor_sync(0xffffffffu, pA1, o);
            pA2 += __shfl_xor_sync(0xffffffffu, pA2, o);
            pB1 += __shfl_xor_sync(0xffffffffu, pB1, o);
            pB2 += __shfl_xor_sync(0xffffffffu, pB2, o);
        }
        if ((lane & 3) == 0) {
            int rA = wr*64 + mt*16 + (lane >> 2);
            atomicAdd(&s_s1[rA],     pA1);
            atomicAdd(&s_s2[rA],     pA2);
            atomicAdd(&s_s1[rA + 8], pB1);
            atomicAdd(&s_s2[rA + 8], pB2);
        }
    }
    __syncthreads();

    // normalize + write: warp writes its 32-col slice for its 64-row band
    {
        int cb = wc*32 + 2*(lane & 3);
        float gv[4][2], bv[4][2];
        #pragma unroll
        for (int nt = 0; nt < 4; nt++) {
            gv[nt][0] = gamma[cb + nt*8];  gv[nt][1] = gamma[cb + nt*8 + 1];
            bv[nt][0] = beta[cb + nt*8];   bv[nt][1] = beta[cb + nt*8 + 1];
        }
        #pragma unroll
        for (int mt = 0; mt < 4; mt++) {
            int rA = wr*64 + mt*16 + (lane >> 2);
            int rB = rA + 8;
            float muA = s_s1[rA] * (1.0f/128.0f);
            float vrA = s_s2[rA] * (1.0f/128.0f) - muA*muA;
            float ivA = 1.0f / sqrtf(vrA + 1e-5f);
            float muB = s_s1[rB] * (1.0f/128.0f);
            float vrB = s_s2[rB] * (1.0f/128.0f) - muB*muB;
            float ivB = 1.0f / sqrtf(vrB + 1e-5f);
            float* opA = out + ((size_t)row0*Kv + rA) * CD;
            float* opB = out + ((size_t)row0*Kv + rB) * CD;
            #pragma unroll
            for (int nt = 0; nt < 4; nt++) {
                int c = cb + nt*8;
                float2 oA, oB;
                oA.x = (acc[mt][nt][0] - muA)*ivA*gv[nt][0] + bv[nt][0];
                oA.y = (acc[mt][nt][1] - muA)*ivA*gv[nt][1] + bv[nt][1];
                oB.x = (acc[mt][nt][2] - muB)*ivB*gv[nt][0] + bv[nt][0];
                oB.y = (acc[mt][nt][3] - muB)*ivB*gv[nt][1] + bv[nt][1];
                *(float2*)(opA + c) = oA;
                *(float2*)(opB + c) = oB;
            }
        }
    }
}

// ---------------------------------------------------------------------------
// Launch
// ---------------------------------------------------------------------------
extern "C" void kernel_launch(void* const* d_in, const int* in_sizes, int n_in,
                              void* d_out, int out_size) {
    const float* X     = (const float*)d_in[0];
    const float* mask  = (const float*)d_in[1];
    const int*   ridx  = (const int*)  d_in[2];
    const int*   chl   = (const int*)  d_in[3];
    const float* Wpos  = (const float*)d_in[4];
    const float* bpos  = (const float*)d_in[5];
    const float* Wedge = (const float*)d_in[6];
    const float* gamma = (const float*)d_in[7];
    const float* beta  = (const float*)d_in[8];
    float* out = (float*)d_out;

    const int k2_smem = (Lv*3 + 4*Lv)*4 + 4*256*8;   // 65536 B
    cudaFuncSetAttribute(k2_topk, cudaFuncAttributeMaxDynamicSharedMemorySize, k2_smem);
    cudaFuncSetAttribute(k3_mma,  cudaFuncAttributeMaxDynamicSharedMemorySize, S_TOT);

    k0_prepW<<<(NKSG*16*32 + 255)/256, 256>>>(Wedge);
    k1_atoms<<<(Bv*Lv + 255)/256, 256>>>(X);
    k2_topk<<<Bv*Lv/4, 256, k2_smem>>>(mask);

    long long e_elems = (long long)Bv*Lv*Kv*CD;
    int write_idx = ((long long)out_size >= e_elems + (long long)Bv*Lv*Kv) ? 1 : 0;
    k3_mma<<<GRID3, 256, S_TOT>>>(ridx, chl, Wpos, bpos, gamma, beta, out, write_idx);
}